// round 5
// baseline (speedup 1.0000x reference)
#include <cuda_runtime.h>

// QLayerNorm: B=4, S=8192, D=1024, fp32. Grid-persistent warp-per-row.
// 592 CTAs (148 SMs x 4 resident) x 8 warps = 4736 warps; each warp loops
// over rows strided by 4736 (~7 rows each). Single wave -> no wave-transition
// overhead. Per row: 8 float4 streaming loads, shfl-xor butterfly reduction,
// scalar epilogue (1 divide + FMA recurrence), 8 float4 streaming stores.
//
// Reference std recurrence (divisor is ALWAYS a):
//   l1=(a/a+a)*.5 ; l2=(l1/a+a)*.5 ; l3=(l2/a+a)*.5 ; std=(l3/a+a)*.5
// Implemented with inv_a = 1/a computed once (fp32 delta ~1e-7, tol 1e-3).

#define D 1024
#define WARPS_PER_CTA 8
#define THREADS (WARPS_PER_CTA * 32)
#define NUM_CTAS 592            // 148 SMs * 4 CTAs/SM -> exactly one wave
#define TOTAL_WARPS (NUM_CTAS * WARPS_PER_CTA)
#define VPL 8                   // float4 per lane (D / (32*4))
#define EPS 5e-05f

__global__ __launch_bounds__(THREADS) void qlayernorm_kernel(
    const float* __restrict__ x,
    const float* __restrict__ weight,
    const float* __restrict__ bias,
    float* __restrict__ out,
    int rows)
{
    const int warp  = threadIdx.x >> 5;
    const int lane  = threadIdx.x & 31;
    const int gwarp = blockIdx.x * WARPS_PER_CTA + warp;

    for (int row = gwarp; row < rows; row += TOTAL_WARPS) {
        const float* xr   = x   + (long long)row * D;
        float*       orow = out + (long long)row * D;

        // Front-batched streaming loads: 8 independent float4 per lane
        float4 v[VPL];
        #pragma unroll
        for (int i = 0; i < VPL; i++) {
            v[i] = __ldcs(reinterpret_cast<const float4*>(xr + (i * 32 + lane) * 4));
        }

        // Per-lane partial sums
        float s = 0.0f, ss = 0.0f;
        #pragma unroll
        for (int i = 0; i < VPL; i++) {
            s  += v[i].x + v[i].y + v[i].z + v[i].w;
            ss += v[i].x * v[i].x + v[i].y * v[i].y
                + v[i].z * v[i].z + v[i].w * v[i].w;
        }

        // Butterfly reduction: every lane ends with the full row sums
        #pragma unroll
        for (int off = 16; off > 0; off >>= 1) {
            s  += __shfl_xor_sync(0xFFFFFFFFu, s,  off);
            ss += __shfl_xor_sync(0xFFFFFFFFu, ss, off);
        }

        // Scalar epilogue, redundant per lane (FMA pipe has headroom)
        const float inv_d = 1.0f / (float)D;
        float mean = s * inv_d;
        float var  = ss * inv_d - mean * mean;
        float a = var + EPS;
        float inv_a = 1.0f / a;            // single divide
        float half_a = 0.5f * a;
        float t;
        t = fmaf(a * inv_a, 0.5f, half_a);     // l1 = (a/a + a)*0.5
        t = fmaf(t * inv_a, 0.5f, half_a);     // l2
        t = fmaf(t * inv_a, 0.5f, half_a);     // l3
        t = fmaf(t * inv_a, 0.5f, half_a);     // std
        const float rstd = 1.0f / t;

        // Fused normalize + affine, streaming stores
        #pragma unroll
        for (int i = 0; i < VPL; i++) {
            const int col = (i * 32 + lane) * 4;
            float4 w = *reinterpret_cast<const float4*>(weight + col);
            float4 b = *reinterpret_cast<const float4*>(bias   + col);
            float4 o;
            o.x = (v[i].x - mean) * rstd * w.x + b.x;
            o.y = (v[i].y - mean) * rstd * w.y + b.y;
            o.z = (v[i].z - mean) * rstd * w.z + b.z;
            o.w = (v[i].w - mean) * rstd * w.w + b.w;
            __stcs(reinterpret_cast<float4*>(orow + col), o);
        }
    }
}

extern "C" void kernel_launch(void* const* d_in, const int* in_sizes, int n_in,
                              void* d_out, int out_size) {
    const float* x      = (const float*)d_in[0];
    const float* weight = (const float*)d_in[1];
    const float* bias   = (const float*)d_in[2];
    float* out          = (float*)d_out;

    const int rows = in_sizes[0] / D;    // 32768
    qlayernorm_kernel<<<NUM_CTAS, THREADS>>>(x, weight, bias, out, rows);
}